// round 11
// baseline (speedup 1.0000x reference)
#include <cuda_runtime.h>
#include <cuda_bf16.h>
#include <math_constants.h>
#include <cstdint>

#define N 8192
#define D 64
#define LOG2E 1.4426950408889634f

// ---------------- scratch (static device memory; no allocation) ----------------
__device__ __align__(128) float g_Q[2 * N * D];            // fp32, 0.125 folded
// K packed: [set][key][ks^(key&7)][tg] float4 {Khi(k=ks*8+tg), Khi(k+4), Klo(k), Klo(k+4)}
__device__ __align__(128) float4 g_kpk[2 * N * 32];
// V^T packed per tile: [set][tile][d][j^(d&3)][tg] uint4
//   {vhi(2tg,2tg+1), vhi(2tg+8,+9), vlo(2tg..), vlo(2tg+8..)} keys relative to j*16 within tile
__device__ __align__(128) uint4 g_vpk[2 * 128 * 64 * 16];
// attention out packed: [set][row][ks^(row&7)][tg] float4 {Ahi(k),Ahi(k+4),Alo(k),Alo(k+4)}
__device__ __align__(128) float4 g_apk[2 * N * 32];
__device__ __align__(128) float g_nrm[2 * N];

// ---------------- helpers ----------------
__device__ __forceinline__ float ex2f(float x) {
    float r;
    asm("ex2.approx.ftz.f32 %0, %1;" : "=f"(r) : "f"(x));
    return r;
}
__device__ __forceinline__ uint32_t f2tf(float v) {
    uint32_t r;
    asm("cvt.rna.tf32.f32 %0, %1;" : "=r"(r) : "f"(v));
    return r;
}
__device__ __forceinline__ float tf32f(float v) { return __uint_as_float(f2tf(v)); }
__device__ __forceinline__ uint32_t pkbf2(float a, float b) {
    uint32_t r;
    asm("cvt.rn.bf16x2.f32 %0, %1, %2;" : "=r"(r) : "f"(b), "f"(a));
    return r;
}
__device__ __forceinline__ float bflo_f(uint32_t v) { return __uint_as_float(v << 16); }
__device__ __forceinline__ float bfhi_f(uint32_t v) { return __uint_as_float(v & 0xffff0000u); }

__device__ __forceinline__ void mma_tf(float* c, const uint32_t* a, uint32_t b0, uint32_t b1) {
    asm volatile(
        "mma.sync.aligned.m16n8k8.row.col.f32.tf32.tf32.f32 "
        "{%0,%1,%2,%3},{%4,%5,%6,%7},{%8,%9},{%0,%1,%2,%3};"
        : "+f"(c[0]), "+f"(c[1]), "+f"(c[2]), "+f"(c[3])
        : "r"(a[0]), "r"(a[1]), "r"(a[2]), "r"(a[3]), "r"(b0), "r"(b1));
}
__device__ __forceinline__ void mma_bf(float* c, const uint32_t* a, uint32_t b0, uint32_t b1) {
    asm volatile(
        "mma.sync.aligned.m16n8k16.row.col.f32.bf16.bf16.f32 "
        "{%0,%1,%2,%3},{%4,%5,%6,%7},{%8,%9},{%0,%1,%2,%3};"
        : "+f"(c[0]), "+f"(c[1]), "+f"(c[2]), "+f"(c[3])
        : "r"(a[0]), "r"(a[1]), "r"(a[2]), "r"(a[3]), "r"(b0), "r"(b1));
}
__device__ __forceinline__ uint32_t smem_u32(const void* p) {
    uint32_t a;
    asm("{ .reg .u64 t; cvta.to.shared.u64 t, %1; cvt.u32.u64 %0, t; }" : "=r"(a) : "l"(p));
    return a;
}
__device__ __forceinline__ void cpa16(uint32_t s, const void* g) {
    asm volatile("cp.async.cg.shared.global [%0], [%1], 16;" :: "r"(s), "l"(g));
}
__device__ __forceinline__ void cp_commit() { asm volatile("cp.async.commit_group;" ::: "memory"); }
__device__ __forceinline__ void cp_wait0() { asm volatile("cp.async.wait_group 0;" ::: "memory"); }
__device__ __forceinline__ void cp_wait1() { asm volatile("cp.async.wait_group 1;" ::: "memory"); }
__device__ __forceinline__ uint32_t fu(float v) { return __float_as_uint(v); }

// ---------------- kernel 1: projections + packed splits (32 rows/block) ----------------
__global__ __launch_bounds__(256) void proj_kernel(const float* __restrict__ x,
                                                   const float* __restrict__ y,
                                                   const float* __restrict__ Wq,
                                                   const float* __restrict__ Wk) {
    __shared__ float sW0[64][65], sW1[64][65];
    __shared__ float sIn[32][64];
    int tid = threadIdx.x;
    int base = blockIdx.x * 32;
    int set = base < N ? 0 : 1;
    int r0 = set ? base - N : base;
    const float* src = (set ? y : x) + (size_t)r0 * D;

    for (int idx = tid; idx < 4096; idx += 256) {
        sW0[idx >> 6][idx & 63] = Wq[idx];
        sW1[idx >> 6][idx & 63] = Wk[idx];
    }
#pragma unroll
    for (int e = 0; e < 8; ++e) {
        int idx = tid + 256 * e;
        int row = idx >> 6, d = idx & 63;
        float v = src[idx];
        sIn[row][d] = v;
        // V^T packed write
        int n = r0 + row;
        int tile = n >> 6, kk = n & 63;
        int jj = kk >> 4, rem = kk & 15;
        int b1 = rem >> 3, tg = (rem & 7) >> 1, lob = rem & 1;
        __nv_bfloat16 h = __float2bfloat16(v);
        __nv_bfloat16 l = __float2bfloat16(v - __bfloat162float(h));
        char* cb = (char*)g_vpk +
                   (size_t)((((set * 128 + tile) * 64 + d) * 16 + ((jj ^ (d & 3)) << 2) + tg)) * 16;
        *(__nv_bfloat16*)(cb + b1 * 4 + lob * 2) = h;
        *(__nv_bfloat16*)(cb + 8 + b1 * 4 + lob * 2) = l;
    }
    __syncthreads();

    int j = tid & 63, rl = tid >> 6;
    float fq[8], fk[8];
#pragma unroll
    for (int i = 0; i < 8; ++i) { fq[i] = 0.f; fk[i] = 0.f; }
#pragma unroll
    for (int k = 0; k < 64; ++k) {
        float wq = sW0[k][j], wk = sW1[k][j];
#pragma unroll
        for (int i = 0; i < 8; ++i) {
            float v = sIn[rl + 4 * i][k];
            fq[i] = fmaf(v, wq, fq[i]);
            fk[i] = fmaf(v, wk, fk[i]);
        }
    }
    int ks = j >> 3, rr = j & 7, tg = rr & 3, h1 = rr >> 2;
#pragma unroll
    for (int i = 0; i < 8; ++i) {
        int n = r0 + rl + 4 * i;
        g_Q[((size_t)set * N + n) * D + j] = fq[i] * 0.125f;  // fold 1/sqrt(64)
        float kh = tf32f(fk[i]);
        float kl = tf32f(fk[i] - kh);
        float* kb = (float*)g_kpk +
                    ((((size_t)set * N + n) * 32 + ((ks ^ (n & 7)) << 2) + tg) << 2);
        kb[h1] = kh;
        kb[2 + h1] = kl;
    }
}

// ---------------- kernel 2: sparse flash attention via mma.sync ----------------
// 128 blocks (2 sets x 64 q-tiles of 128), 8 warps. Key tile 64.
// Phase 1: hh tf32 product -> approx max; skip tile if warp-max < warp-min-running-max - 28.
// Phase 2 (surviving tiles): correction products, softmax, bf16 split PV.
#define SQ 0
#define SK 34816
#define SV 100352
#define ATTN_SMEM 133120

__global__ __launch_bounds__(256, 1) void attn_kernel() {
    extern __shared__ __align__(16) char sm[];
    uint32_t sb = smem_u32(sm);
    int tid = threadIdx.x, wid = tid >> 5, lane = tid & 31;
    int g = lane >> 2, tg = lane & 3;
    int set = blockIdx.x >> 6;
    int m0 = (int)(blockIdx.x & 63) * 128;

    const float* Qg = g_Q + ((size_t)set * N + m0) * D;
    const float4* Kg = g_kpk + (size_t)set * N * 32;
    const uint4* Vg = g_vpk + (size_t)set * 128 * 1024;

    // Q tile fp32 (stride 68)
    {
        float* s = (float*)(sm + SQ);
#pragma unroll
        for (int ci = tid; ci < 2048; ci += 256) {
            int row = ci >> 4, u = ci & 15;
            *(float4*)(s + row * 68 + u * 4) = *(const float4*)(Qg + row * 64 + u * 4);
        }
    }
    // prefetch tile 0
#pragma unroll
    for (int ci = tid; ci < 2048; ci += 256) cpa16(sb + SK + ci * 16, Kg + ci);
#pragma unroll
    for (int ci = tid; ci < 1024; ci += 256) cpa16(sb + SV + ci * 16, Vg + ci);
    cp_commit();
    __syncthreads();

    // Q fragments, tf32 hi/lo
    uint32_t qh[8][4], ql[8][4];
    {
        const float* sQ = (const float*)(sm + SQ);
        int r0 = wid * 16 + g;
#pragma unroll
        for (int ksq = 0; ksq < 8; ++ksq) {
            float v0 = sQ[r0 * 68 + ksq * 8 + tg];
            float v1 = sQ[(r0 + 8) * 68 + ksq * 8 + tg];
            float v2 = sQ[r0 * 68 + ksq * 8 + tg + 4];
            float v3 = sQ[(r0 + 8) * 68 + ksq * 8 + tg + 4];
            qh[ksq][0] = f2tf(v0); ql[ksq][0] = f2tf(v0 - __uint_as_float(qh[ksq][0]));
            qh[ksq][1] = f2tf(v1); ql[ksq][1] = f2tf(v1 - __uint_as_float(qh[ksq][1]));
            qh[ksq][2] = f2tf(v2); ql[ksq][2] = f2tf(v2 - __uint_as_float(qh[ksq][2]));
            qh[ksq][3] = f2tf(v3); ql[ksq][3] = f2tf(v3 - __uint_as_float(qh[ksq][3]));
        }
    }

    float o[8][4];
#pragma unroll
    for (int db = 0; db < 8; ++db)
#pragma unroll
        for (int q = 0; q < 4; ++q) o[db][q] = 0.f;
    float mr0 = -CUDART_INF_F, mr1 = -CUDART_INF_F;
    float l0 = 0.f, l1 = 0.f;

#pragma unroll 1
    for (int kt = 0; kt < 128; ++kt) {
        int b = kt & 1;
        if (kt < 127) {
            const float4* kn = Kg + (size_t)(kt + 1) * 2048;
            const uint4* vn = Vg + (size_t)(kt + 1) * 1024;
#pragma unroll
            for (int ci = tid; ci < 2048; ci += 256)
                cpa16(sb + SK + (b ^ 1) * 32768 + ci * 16, kn + ci);
#pragma unroll
            for (int ci = tid; ci < 1024; ci += 256)
                cpa16(sb + SV + (b ^ 1) * 16384 + ci * 16, vn + ci);
            cp_commit();
            cp_wait1();
        } else {
            cp_wait0();
        }
        __syncthreads();
        const float4* KP = (const float4*)(sm + SK + b * 32768);
        const uint4* VP = (const uint4*)(sm + SV + b * 16384);

        // ---- phase 1: hh only ----
        float sc[8][4];
#pragma unroll
        for (int nb = 0; nb < 8; ++nb)
#pragma unroll
            for (int q = 0; q < 4; ++q) sc[nb][q] = 0.f;
#pragma unroll
        for (int nb = 0; nb < 8; ++nb) {
            const float4* kr = KP + (nb * 8 + g) * 32 + tg;
#pragma unroll
            for (int ksq = 0; ksq < 8; ++ksq) {
                float4 kv = kr[(ksq ^ g) << 2];
                mma_tf(sc[nb], qh[ksq], fu(kv.x), fu(kv.y));
            }
        }
        // warp-level skip decision
        float tmax = sc[0][0];
#pragma unroll
        for (int nb = 0; nb < 8; ++nb)
#pragma unroll
            for (int q = 0; q < 4; ++q) tmax = fmaxf(tmax, sc[nb][q]);
        float rmin = fminf(mr0, mr1);
#pragma unroll
        for (int sh = 1; sh < 32; sh <<= 1) {
            tmax = fmaxf(tmax, __shfl_xor_sync(0xffffffffu, tmax, sh));
            rmin = fminf(rmin, __shfl_xor_sync(0xffffffffu, rmin, sh));
        }
        if (tmax >= rmin - 28.0f) {
            // ---- phase 2: corrections ----
#pragma unroll
            for (int nb = 0; nb < 8; ++nb) {
                const float4* kr = KP + (nb * 8 + g) * 32 + tg;
#pragma unroll
                for (int ksq = 0; ksq < 8; ++ksq) {
                    float4 kv = kr[(ksq ^ g) << 2];
                    mma_tf(sc[nb], qh[ksq], fu(kv.z), fu(kv.w));
                    mma_tf(sc[nb], ql[ksq], fu(kv.x), fu(kv.y));
                }
            }
            // ---- online softmax ----
            float mt0 = sc[0][0], mt1 = sc[0][2];
#pragma unroll
            for (int nb = 0; nb < 8; ++nb) {
                mt0 = fmaxf(mt0, fmaxf(sc[nb][0], sc[nb][1]));
                mt1 = fmaxf(mt1, fmaxf(sc[nb][2], sc[nb][3]));
            }
            mt0 = fmaxf(mt0, __shfl_xor_sync(0xffffffffu, mt0, 1));
            mt0 = fmaxf(mt0, __shfl_xor_sync(0xffffffffu, mt0, 2));
            mt1 = fmaxf(mt1, __shfl_xor_sync(0xffffffffu, mt1, 1));
            mt1 = fmaxf(mt1, __shfl_xor_sync(0xffffffffu, mt1, 2));
            float mn0 = fmaxf(mr0, mt0), mn1 = fmaxf(mr1, mt1);
            float s0 = ex2f((mr0 - mn0) * LOG2E);
            float s1 = ex2f((mr1 - mn1) * LOG2E);
            l0 *= s0; l1 *= s1;
#pragma unroll
            for (int db = 0; db < 8; ++db) {
                o[db][0] *= s0; o[db][1] *= s0;
                o[db][2] *= s1; o[db][3] *= s1;
            }
            mr0 = mn0; mr1 = mn1;
            uint32_t ph[8][2], pl[8][2];
#pragma unroll
            for (int nb = 0; nb < 8; ++nb) {
                float p0 = ex2f((sc[nb][0] - mn0) * LOG2E);
                float p1 = ex2f((sc[nb][1] - mn0) * LOG2E);
                float p2 = ex2f((sc[nb][2] - mn1) * LOG2E);
                float p3 = ex2f((sc[nb][3] - mn1) * LOG2E);
                l0 += p0 + p1; l1 += p2 + p3;
                uint32_t h0 = pkbf2(p0, p1), h1 = pkbf2(p2, p3);
                ph[nb][0] = h0; pl[nb][0] = pkbf2(p0 - bflo_f(h0), p1 - bfhi_f(h0));
                ph[nb][1] = h1; pl[nb][1] = pkbf2(p2 - bflo_f(h1), p3 - bfhi_f(h1));
            }
            // ---- O += P V ----
#pragma unroll
            for (int j = 0; j < 4; ++j) {
                uint32_t ah[4] = {ph[2 * j][0], ph[2 * j][1], ph[2 * j + 1][0], ph[2 * j + 1][1]};
                uint32_t al[4] = {pl[2 * j][0], pl[2 * j][1], pl[2 * j + 1][0], pl[2 * j + 1][1]};
#pragma unroll
                for (int db = 0; db < 8; ++db) {
                    uint4 vv = VP[(db * 8 + g) * 16 + ((j ^ (g & 3)) << 2) + tg];
                    mma_bf(o[db], ah, vv.x, vv.y);
                    mma_bf(o[db], ah, vv.z, vv.w);
                    mma_bf(o[db], al, vv.x, vv.y);
                }
            }
        }
        __syncthreads();
    }

    // ---- epilogue: normalize, packed splits, norms ----
    l0 += __shfl_xor_sync(0xffffffffu, l0, 1);
    l0 += __shfl_xor_sync(0xffffffffu, l0, 2);
    l1 += __shfl_xor_sync(0xffffffffu, l1, 1);
    l1 += __shfl_xor_sync(0xffffffffu, l1, 2);
    float i0 = 1.0f / l0, i1 = 1.0f / l1;
    int r0 = m0 + wid * 16 + g, r1 = r0 + 8;
    size_t row0 = (size_t)set * N + r0, row1 = (size_t)set * N + r1;
    float* ab = (float*)g_apk;
    float nr0 = 0.f, nr1 = 0.f;
#pragma unroll
    for (int db = 0; db < 8; ++db) {
        float v0 = o[db][0] * i0, v1 = o[db][1] * i0;
        float v2 = o[db][2] * i1, v3 = o[db][3] * i1;
        nr0 = fmaf(v0, v0, fmaf(v1, v1, nr0));
        nr1 = fmaf(v2, v2, fmaf(v3, v3, nr1));
#pragma unroll
        for (int e = 0; e < 2; ++e) {
            int k = db * 8 + 2 * tg + e;
            int rr2 = k & 7, tgp = rr2 & 3, h1 = rr2 >> 2;
            float va = e ? v1 : v0, vb = e ? v3 : v2;
            float ha = tf32f(va), hb = tf32f(vb);
            size_t fo0 = (row0 * 32 + (size_t)(((db ^ (r0 & 7)) << 2) + tgp)) << 2;
            size_t fo1 = (row1 * 32 + (size_t)(((db ^ (r1 & 7)) << 2) + tgp)) << 2;
            ab[fo0 + h1] = ha; ab[fo0 + 2 + h1] = tf32f(va - ha);
            ab[fo1 + h1] = hb; ab[fo1 + 2 + h1] = tf32f(vb - hb);
        }
    }
    nr0 += __shfl_xor_sync(0xffffffffu, nr0, 1);
    nr0 += __shfl_xor_sync(0xffffffffu, nr0, 2);
    nr1 += __shfl_xor_sync(0xffffffffu, nr1, 1);
    nr1 += __shfl_xor_sync(0xffffffffu, nr1, 2);
    if (tg == 0) {
        g_nrm[set * N + r0] = nr0;
        g_nrm[set * N + r1] = nr1;
    }
}

// ---------------- kernel 3: RBF via mma.sync, packed fragments ----------------
#define RX 0
#define RY 65536
#define RNX 131072
#define RNY 131584
#define RBF_SMEM 132096

__global__ __launch_bounds__(256, 1) void rbf_kernel(float* __restrict__ out) {
    extern __shared__ __align__(16) char sm[];
    uint32_t sb = smem_u32(sm);
    int tid = threadIdx.x, wid = tid >> 5, lane = tid & 31;
    int g = lane >> 2, tg = lane & 3;
    int i0 = blockIdx.y * 128, j0 = blockIdx.x * 128;

    const float4* Xg = g_apk + (size_t)i0 * 32;
    const float4* Yg = g_apk + ((size_t)N + j0) * 32;
#pragma unroll
    for (int ci = tid; ci < 4096; ci += 256) {
        cpa16(sb + RX + ci * 16, Xg + ci);
        cpa16(sb + RY + ci * 16, Yg + ci);
    }
    cp_commit();
    if (tid < 128) {
        ((float*)(sm + RNX))[tid] = g_nrm[i0 + tid];
        ((float*)(sm + RNY))[tid] = g_nrm[N + j0 + tid];
    }
    cp_wait0();
    __syncthreads();

    const float4* XP = (const float4*)(sm + RX);
    const float4* YP = (const float4*)(sm + RY);

    uint32_t ah[8][4], al[8][4];
    int r0 = wid * 16 + g;
#pragma unroll
    for (int ksq = 0; ksq < 8; ++ksq) {
        float4 a0 = XP[r0 * 32 + ((ksq ^ (r0 & 7)) << 2) + tg];
        float4 a8 = XP[(r0 + 8) * 32 + ((ksq ^ (r0 & 7)) << 2) + tg];
        ah[ksq][0] = fu(a0.x); ah[ksq][1] = fu(a8.x); ah[ksq][2] = fu(a0.y); ah[ksq][3] = fu(a8.y);
        al[ksq][0] = fu(a0.z); al[ksq][1] = fu(a8.z); al[ksq][2] = fu(a0.w); al[ksq][3] = fu(a8.w);
    }

    float c[16][4];
#pragma unroll
    for (int nb = 0; nb < 16; ++nb)
#pragma unroll
        for (int q = 0; q < 4; ++q) c[nb][q] = 0.f;

#pragma unroll
    for (int nb = 0; nb < 16; ++nb) {
        const float4* yr = YP + (nb * 8 + g) * 32 + tg;
#pragma unroll
        for (int ksq = 0; ksq < 8; ++ksq) {
            float4 bv = yr[(ksq ^ g) << 2];
            mma_tf(c[nb], ah[ksq], fu(bv.x), fu(bv.y));
            mma_tf(c[nb], ah[ksq], fu(bv.z), fu(bv.w));
            mma_tf(c[nb], al[ksq], fu(bv.x), fu(bv.y));
        }
    }

    const float* snx = (const float*)(sm + RNX);
    const float* sny = (const float*)(sm + RNY);
    float nx0 = snx[r0], nx1 = snx[r0 + 8];
    float* out0 = out + (size_t)(i0 + r0) * N + j0;
    float* out1 = out0 + (size_t)8 * N;
#pragma unroll
    for (int nb = 0; nb < 16; ++nb) {
        int col = nb * 8 + 2 * tg;
        float ny0 = sny[col], ny1 = sny[col + 1];
        float a0 = fmaf(2.f, c[nb][0], -nx0 - ny0);
        float a1 = fmaf(2.f, c[nb][1], -nx0 - ny1);
        float a2 = fmaf(2.f, c[nb][2], -nx1 - ny0);
        float a3 = fmaf(2.f, c[nb][3], -nx1 - ny1);
        *(float2*)(out0 + col) = make_float2(ex2f(a0 * LOG2E), ex2f(a1 * LOG2E));
        *(float2*)(out1 + col) = make_float2(ex2f(a2 * LOG2E), ex2f(a3 * LOG2E));
    }
}

// ---------------- launch ----------------
extern "C" void kernel_launch(void* const* d_in, const int* in_sizes, int n_in,
                              void* d_out, int out_size) {
    const float* Wq = (const float*)d_in[0];  // rotation_params
    const float* Wk = (const float*)d_in[1];  // entangle_params
    const float* x = (const float*)d_in[2];
    const float* y = (const float*)d_in[3];
    float* out = (float*)d_out;

    cudaFuncSetAttribute(attn_kernel, cudaFuncAttributeMaxDynamicSharedMemorySize, ATTN_SMEM);
    cudaFuncSetAttribute(rbf_kernel, cudaFuncAttributeMaxDynamicSharedMemorySize, RBF_SMEM);

    proj_kernel<<<(2 * N) / 32, 256>>>(x, y, Wq, Wk);
    attn_kernel<<<128, 256, ATTN_SMEM>>>();
    rbf_kernel<<<dim3(64, 64), 256, RBF_SMEM>>>(out);
}

// round 12
// speedup vs baseline: 1.5583x; 1.5583x over previous
#include <cuda_runtime.h>
#include <cuda_bf16.h>
#include <math_constants.h>
#include <cstdint>

#define N 8192
#define D 64
#define LOG2E 1.4426950408889634f

// ---------------- scratch (static device memory; no allocation) ----------------
__device__ __align__(128) float g_Q[2 * N * D];            // fp32, 0.125 folded
// K packed: [set][key][ks^(key&7)][tg] float4 {Khi(k=ks*8+tg), Khi(k+4), Klo(k), Klo(k+4)}
__device__ __align__(128) float4 g_kpk[2 * N * 32];
// V^T packed per tile: [set][tile][d][j^(d&3)][tg] uint4
//   {vhi(2tg,2tg+1), vhi(2tg+8,+9), vlo(2tg..), vlo(2tg+8..)} keys relative to j*16 within tile
__device__ __align__(128) uint4 g_vpk[2 * 128 * 64 * 16];
// attention out packed: [set][row][ks^(row&7)][tg] float4 {Ahi(k),Ahi(k+4),Alo(k),Alo(k+4)}
__device__ __align__(128) float4 g_apk[2 * N * 32];
__device__ __align__(128) float g_nrm[2 * N];

// ---------------- helpers ----------------
__device__ __forceinline__ float ex2f(float x) {
    float r;
    asm("ex2.approx.ftz.f32 %0, %1;" : "=f"(r) : "f"(x));
    return r;
}
__device__ __forceinline__ uint32_t f2tf(float v) {
    uint32_t r;
    asm("cvt.rna.tf32.f32 %0, %1;" : "=r"(r) : "f"(v));
    return r;
}
__device__ __forceinline__ float tf32f(float v) { return __uint_as_float(f2tf(v)); }
__device__ __forceinline__ uint32_t pkbf2(float a, float b) {
    uint32_t r;
    asm("cvt.rn.bf16x2.f32 %0, %1, %2;" : "=r"(r) : "f"(b), "f"(a));
    return r;
}
__device__ __forceinline__ float bflo_f(uint32_t v) { return __uint_as_float(v << 16); }
__device__ __forceinline__ float bfhi_f(uint32_t v) { return __uint_as_float(v & 0xffff0000u); }

__device__ __forceinline__ void mma_tf(float* c, const uint32_t* a, uint32_t b0, uint32_t b1) {
    asm volatile(
        "mma.sync.aligned.m16n8k8.row.col.f32.tf32.tf32.f32 "
        "{%0,%1,%2,%3},{%4,%5,%6,%7},{%8,%9},{%0,%1,%2,%3};"
        : "+f"(c[0]), "+f"(c[1]), "+f"(c[2]), "+f"(c[3])
        : "r"(a[0]), "r"(a[1]), "r"(a[2]), "r"(a[3]), "r"(b0), "r"(b1));
}
__device__ __forceinline__ void mma_bf(float* c, const uint32_t* a, uint32_t b0, uint32_t b1) {
    asm volatile(
        "mma.sync.aligned.m16n8k16.row.col.f32.bf16.bf16.f32 "
        "{%0,%1,%2,%3},{%4,%5,%6,%7},{%8,%9},{%0,%1,%2,%3};"
        : "+f"(c[0]), "+f"(c[1]), "+f"(c[2]), "+f"(c[3])
        : "r"(a[0]), "r"(a[1]), "r"(a[2]), "r"(a[3]), "r"(b0), "r"(b1));
}
__device__ __forceinline__ uint32_t smem_u32(const void* p) {
    uint32_t a;
    asm("{ .reg .u64 t; cvta.to.shared.u64 t, %1; cvt.u32.u64 %0, t; }" : "=r"(a) : "l"(p));
    return a;
}
__device__ __forceinline__ void cpa16(uint32_t s, const void* g) {
    asm volatile("cp.async.cg.shared.global [%0], [%1], 16;" :: "r"(s), "l"(g));
}
__device__ __forceinline__ void cp_commit() { asm volatile("cp.async.commit_group;" ::: "memory"); }
__device__ __forceinline__ void cp_wait0() { asm volatile("cp.async.wait_group 0;" ::: "memory"); }
__device__ __forceinline__ void cp_wait1() { asm volatile("cp.async.wait_group 1;" ::: "memory"); }
__device__ __forceinline__ uint32_t fu(float v) { return __float_as_uint(v); }

// ---------------- kernel 1: projections + packed splits (32 rows/block) ----------------
__global__ __launch_bounds__(256) void proj_kernel(const float* __restrict__ x,
                                                   const float* __restrict__ y,
                                                   const float* __restrict__ Wq,
                                                   const float* __restrict__ Wk) {
    __shared__ float sW0[64][65], sW1[64][65];
    __shared__ float sIn[32][64];
    int tid = threadIdx.x;
    int base = blockIdx.x * 32;
    int set = base < N ? 0 : 1;
    int r0 = set ? base - N : base;
    const float* src = (set ? y : x) + (size_t)r0 * D;

    for (int idx = tid; idx < 4096; idx += 256) {
        sW0[idx >> 6][idx & 63] = Wq[idx];
        sW1[idx >> 6][idx & 63] = Wk[idx];
    }
#pragma unroll
    for (int e = 0; e < 8; ++e) {
        int idx = tid + 256 * e;
        int row = idx >> 6, d = idx & 63;
        float v = src[idx];
        sIn[row][d] = v;
        // V^T packed write
        int n = r0 + row;
        int tile = n >> 6, kk = n & 63;
        int jj = kk >> 4, rem = kk & 15;
        int b1 = rem >> 3, tg = (rem & 7) >> 1, lob = rem & 1;
        __nv_bfloat16 h = __float2bfloat16(v);
        __nv_bfloat16 l = __float2bfloat16(v - __bfloat162float(h));
        char* cb = (char*)g_vpk +
                   (size_t)((((set * 128 + tile) * 64 + d) * 16 + ((jj ^ (d & 3)) << 2) + tg)) * 16;
        *(__nv_bfloat16*)(cb + b1 * 4 + lob * 2) = h;
        *(__nv_bfloat16*)(cb + 8 + b1 * 4 + lob * 2) = l;
    }
    __syncthreads();

    int j = tid & 63, rl = tid >> 6;
    float fq[8], fk[8];
#pragma unroll
    for (int i = 0; i < 8; ++i) { fq[i] = 0.f; fk[i] = 0.f; }
#pragma unroll
    for (int k = 0; k < 64; ++k) {
        float wq = sW0[k][j], wk = sW1[k][j];
#pragma unroll
        for (int i = 0; i < 8; ++i) {
            float v = sIn[rl + 4 * i][k];
            fq[i] = fmaf(v, wq, fq[i]);
            fk[i] = fmaf(v, wk, fk[i]);
        }
    }
    int ks = j >> 3, rr = j & 7, tg = rr & 3, h1 = rr >> 2;
#pragma unroll
    for (int i = 0; i < 8; ++i) {
        int n = r0 + rl + 4 * i;
        g_Q[((size_t)set * N + n) * D + j] = fq[i] * 0.125f;  // fold 1/sqrt(64)
        float kh = tf32f(fk[i]);
        float kl = tf32f(fk[i] - kh);
        float* kb = (float*)g_kpk +
                    ((((size_t)set * N + n) * 32 + ((ks ^ (n & 7)) << 2) + tg) << 2);
        kb[h1] = kh;
        kb[2 + h1] = kl;
    }
}

// ---------------- kernel 2: flash attention via mma.sync (single phase, packed LDS.128) ----------------
// 128 blocks (2 sets x 64 q-tiles of 128 rows), 8 warps x 16 q-rows. Key tile 64.
// S: tf32 3-product split, one float4 LDS feeds all 3 MMAs. PV: bf16 3-product, one uint4 LDS.
#define SQ 0
#define SK 34816
#define SV 100352
#define ATTN_SMEM 133120

__global__ __launch_bounds__(256, 1) void attn_kernel() {
    extern __shared__ __align__(16) char sm[];
    uint32_t sb = smem_u32(sm);
    int tid = threadIdx.x, wid = tid >> 5, lane = tid & 31;
    int g = lane >> 2, tg = lane & 3;
    int set = blockIdx.x >> 6;
    int m0 = (int)(blockIdx.x & 63) * 128;

    const float* Qg = g_Q + ((size_t)set * N + m0) * D;
    const float4* Kg = g_kpk + (size_t)set * N * 32;
    const uint4* Vg = g_vpk + (size_t)set * 128 * 1024;

    // Q tile fp32 (stride 68)
    {
        float* s = (float*)(sm + SQ);
#pragma unroll
        for (int ci = tid; ci < 2048; ci += 256) {
            int row = ci >> 4, u = ci & 15;
            *(float4*)(s + row * 68 + u * 4) = *(const float4*)(Qg + row * 64 + u * 4);
        }
    }
    // prefetch tile 0
#pragma unroll
    for (int ci = tid; ci < 2048; ci += 256) cpa16(sb + SK + ci * 16, Kg + ci);
#pragma unroll
    for (int ci = tid; ci < 1024; ci += 256) cpa16(sb + SV + ci * 16, Vg + ci);
    cp_commit();
    __syncthreads();

    // Q fragments, tf32 hi/lo
    uint32_t qh[8][4], ql[8][4];
    {
        const float* sQ = (const float*)(sm + SQ);
        int r0 = wid * 16 + g;
#pragma unroll
        for (int ksq = 0; ksq < 8; ++ksq) {
            float v0 = sQ[r0 * 68 + ksq * 8 + tg];
            float v1 = sQ[(r0 + 8) * 68 + ksq * 8 + tg];
            float v2 = sQ[r0 * 68 + ksq * 8 + tg + 4];
            float v3 = sQ[(r0 + 8) * 68 + ksq * 8 + tg + 4];
            qh[ksq][0] = f2tf(v0); ql[ksq][0] = f2tf(v0 - __uint_as_float(qh[ksq][0]));
            qh[ksq][1] = f2tf(v1); ql[ksq][1] = f2tf(v1 - __uint_as_float(qh[ksq][1]));
            qh[ksq][2] = f2tf(v2); ql[ksq][2] = f2tf(v2 - __uint_as_float(qh[ksq][2]));
            qh[ksq][3] = f2tf(v3); ql[ksq][3] = f2tf(v3 - __uint_as_float(qh[ksq][3]));
        }
    }

    float o[8][4];
#pragma unroll
    for (int db = 0; db < 8; ++db)
#pragma unroll
        for (int q = 0; q < 4; ++q) o[db][q] = 0.f;
    float mr0 = -CUDART_INF_F, mr1 = -CUDART_INF_F;
    float l0 = 0.f, l1 = 0.f;

#pragma unroll 1
    for (int kt = 0; kt < 128; ++kt) {
        int b = kt & 1;
        if (kt < 127) {
            const float4* kn = Kg + (size_t)(kt + 1) * 2048;
            const uint4* vn = Vg + (size_t)(kt + 1) * 1024;
#pragma unroll
            for (int ci = tid; ci < 2048; ci += 256)
                cpa16(sb + SK + (b ^ 1) * 32768 + ci * 16, kn + ci);
#pragma unroll
            for (int ci = tid; ci < 1024; ci += 256)
                cpa16(sb + SV + (b ^ 1) * 16384 + ci * 16, vn + ci);
            cp_commit();
            cp_wait1();
        } else {
            cp_wait0();
        }
        __syncthreads();
        const float4* KP = (const float4*)(sm + SK + b * 32768);
        const uint4* VP = (const uint4*)(sm + SV + b * 16384);

        // ---- S = Q K^T : 3 products per float4 load ----
        float sc[8][4];
#pragma unroll
        for (int nb = 0; nb < 8; ++nb)
#pragma unroll
            for (int q = 0; q < 4; ++q) sc[nb][q] = 0.f;
#pragma unroll
        for (int nb = 0; nb < 8; ++nb) {
            const float4* kr = KP + (nb * 8 + g) * 32 + tg;
#pragma unroll
            for (int ksq = 0; ksq < 8; ++ksq) {
                float4 kv = kr[(ksq ^ g) << 2];
                mma_tf(sc[nb], qh[ksq], fu(kv.x), fu(kv.y));
                mma_tf(sc[nb], qh[ksq], fu(kv.z), fu(kv.w));
                mma_tf(sc[nb], ql[ksq], fu(kv.x), fu(kv.y));
            }
        }

        // ---- online softmax ----
        float mt0 = sc[0][0], mt1 = sc[0][2];
#pragma unroll
        for (int nb = 0; nb < 8; ++nb) {
            mt0 = fmaxf(mt0, fmaxf(sc[nb][0], sc[nb][1]));
            mt1 = fmaxf(mt1, fmaxf(sc[nb][2], sc[nb][3]));
        }
        mt0 = fmaxf(mt0, __shfl_xor_sync(0xffffffffu, mt0, 1));
        mt0 = fmaxf(mt0, __shfl_xor_sync(0xffffffffu, mt0, 2));
        mt1 = fmaxf(mt1, __shfl_xor_sync(0xffffffffu, mt1, 1));
        mt1 = fmaxf(mt1, __shfl_xor_sync(0xffffffffu, mt1, 2));
        float mn0 = fmaxf(mr0, mt0), mn1 = fmaxf(mr1, mt1);
        float s0 = ex2f((mr0 - mn0) * LOG2E);
        float s1 = ex2f((mr1 - mn1) * LOG2E);
        l0 *= s0; l1 *= s1;
#pragma unroll
        for (int db = 0; db < 8; ++db) {
            o[db][0] *= s0; o[db][1] *= s0;
            o[db][2] *= s1; o[db][3] *= s1;
        }
        mr0 = mn0; mr1 = mn1;
        uint32_t ph[8][2], pl[8][2];
#pragma unroll
        for (int nb = 0; nb < 8; ++nb) {
            float p0 = ex2f((sc[nb][0] - mn0) * LOG2E);
            float p1 = ex2f((sc[nb][1] - mn0) * LOG2E);
            float p2 = ex2f((sc[nb][2] - mn1) * LOG2E);
            float p3 = ex2f((sc[nb][3] - mn1) * LOG2E);
            l0 += p0 + p1; l1 += p2 + p3;
            uint32_t h0 = pkbf2(p0, p1), h1 = pkbf2(p2, p3);
            ph[nb][0] = h0; pl[nb][0] = pkbf2(p0 - bflo_f(h0), p1 - bfhi_f(h0));
            ph[nb][1] = h1; pl[nb][1] = pkbf2(p2 - bflo_f(h1), p3 - bfhi_f(h1));
        }

        // ---- O += P V : 3 products per uint4 load ----
#pragma unroll
        for (int j = 0; j < 4; ++j) {
            uint32_t ah[4] = {ph[2 * j][0], ph[2 * j][1], ph[2 * j + 1][0], ph[2 * j + 1][1]};
            uint32_t al[4] = {pl[2 * j][0], pl[2 * j][1], pl[2 * j + 1][0], pl[2 * j + 1][1]};
#pragma unroll
            for (int db = 0; db < 8; ++db) {
                uint4 vv = VP[(db * 8 + g) * 16 + ((j ^ (g & 3)) << 2) + tg];
                mma_bf(o[db], ah, vv.x, vv.y);
                mma_bf(o[db], ah, vv.z, vv.w);
                mma_bf(o[db], al, vv.x, vv.y);
            }
        }
        __syncthreads();
    }

    // ---- epilogue: normalize, packed splits, norms ----
    l0 += __shfl_xor_sync(0xffffffffu, l0, 1);
    l0 += __shfl_xor_sync(0xffffffffu, l0, 2);
    l1 += __shfl_xor_sync(0xffffffffu, l1, 1);
    l1 += __shfl_xor_sync(0xffffffffu, l1, 2);
    float i0 = 1.0f / l0, i1 = 1.0f / l1;
    int r0 = m0 + wid * 16 + g, r1 = r0 + 8;
    size_t row0 = (size_t)set * N + r0, row1 = (size_t)set * N + r1;
    float* ab = (float*)g_apk;
    float nr0 = 0.f, nr1 = 0.f;
#pragma unroll
    for (int db = 0; db < 8; ++db) {
        float v0 = o[db][0] * i0, v1 = o[db][1] * i0;
        float v2 = o[db][2] * i1, v3 = o[db][3] * i1;
        nr0 = fmaf(v0, v0, fmaf(v1, v1, nr0));
        nr1 = fmaf(v2, v2, fmaf(v3, v3, nr1));
#pragma unroll
        for (int e = 0; e < 2; ++e) {
            int k = db * 8 + 2 * tg + e;
            int rr2 = k & 7, tgp = rr2 & 3, h1 = rr2 >> 2;
            float va = e ? v1 : v0, vb = e ? v3 : v2;
            float ha = tf32f(va), hb = tf32f(vb);
            size_t fo0 = (row0 * 32 + (size_t)(((db ^ (r0 & 7)) << 2) + tgp)) << 2;
            size_t fo1 = (row1 * 32 + (size_t)(((db ^ (r1 & 7)) << 2) + tgp)) << 2;
            ab[fo0 + h1] = ha; ab[fo0 + 2 + h1] = tf32f(va - ha);
            ab[fo1 + h1] = hb; ab[fo1 + 2 + h1] = tf32f(vb - hb);
        }
    }
    nr0 += __shfl_xor_sync(0xffffffffu, nr0, 1);
    nr0 += __shfl_xor_sync(0xffffffffu, nr0, 2);
    nr1 += __shfl_xor_sync(0xffffffffu, nr1, 1);
    nr1 += __shfl_xor_sync(0xffffffffu, nr1, 2);
    if (tg == 0) {
        g_nrm[set * N + r0] = nr0;
        g_nrm[set * N + r1] = nr1;
    }
}

// ---------------- kernel 3: RBF via mma.sync, packed fragments ----------------
#define RX 0
#define RY 65536
#define RNX 131072
#define RNY 131584
#define RBF_SMEM 132096

__global__ __launch_bounds__(256, 1) void rbf_kernel(float* __restrict__ out) {
    extern __shared__ __align__(16) char sm[];
    uint32_t sb = smem_u32(sm);
    int tid = threadIdx.x, wid = tid >> 5, lane = tid & 31;
    int g = lane >> 2, tg = lane & 3;
    int i0 = blockIdx.y * 128, j0 = blockIdx.x * 128;

    const float4* Xg = g_apk + (size_t)i0 * 32;
    const float4* Yg = g_apk + ((size_t)N + j0) * 32;
#pragma unroll
    for (int ci = tid; ci < 4096; ci += 256) {
        cpa16(sb + RX + ci * 16, Xg + ci);
        cpa16(sb + RY + ci * 16, Yg + ci);
    }
    cp_commit();
    if (tid < 128) {
        ((float*)(sm + RNX))[tid] = g_nrm[i0 + tid];
        ((float*)(sm + RNY))[tid] = g_nrm[N + j0 + tid];
    }
    cp_wait0();
    __syncthreads();

    const float4* XP = (const float4*)(sm + RX);
    const float4* YP = (const float4*)(sm + RY);

    uint32_t ah[8][4], al[8][4];
    int r0 = wid * 16 + g;
#pragma unroll
    for (int ksq = 0; ksq < 8; ++ksq) {
        float4 a0 = XP[r0 * 32 + ((ksq ^ (r0 & 7)) << 2) + tg];
        float4 a8 = XP[(r0 + 8) * 32 + ((ksq ^ (r0 & 7)) << 2) + tg];
        ah[ksq][0] = fu(a0.x); ah[ksq][1] = fu(a8.x); ah[ksq][2] = fu(a0.y); ah[ksq][3] = fu(a8.y);
        al[ksq][0] = fu(a0.z); al[ksq][1] = fu(a8.z); al[ksq][2] = fu(a0.w); al[ksq][3] = fu(a8.w);
    }

    float c[16][4];
#pragma unroll
    for (int nb = 0; nb < 16; ++nb)
#pragma unroll
        for (int q = 0; q < 4; ++q) c[nb][q] = 0.f;

#pragma unroll
    for (int nb = 0; nb < 16; ++nb) {
        const float4* yr = YP + (nb * 8 + g) * 32 + tg;
#pragma unroll
        for (int ksq = 0; ksq < 8; ++ksq) {
            float4 bv = yr[(ksq ^ g) << 2];
            mma_tf(c[nb], ah[ksq], fu(bv.x), fu(bv.y));
            mma_tf(c[nb], ah[ksq], fu(bv.z), fu(bv.w));
            mma_tf(c[nb], al[ksq], fu(bv.x), fu(bv.y));
        }
    }

    const float* snx = (const float*)(sm + RNX);
    const float* sny = (const float*)(sm + RNY);
    float nx0 = snx[r0], nx1 = snx[r0 + 8];
    float* out0 = out + (size_t)(i0 + r0) * N + j0;
    float* out1 = out0 + (size_t)8 * N;
#pragma unroll
    for (int nb = 0; nb < 16; ++nb) {
        int col = nb * 8 + 2 * tg;
        float ny0 = sny[col], ny1 = sny[col + 1];
        float a0 = fmaf(2.f, c[nb][0], -nx0 - ny0);
        float a1 = fmaf(2.f, c[nb][1], -nx0 - ny1);
        float a2 = fmaf(2.f, c[nb][2], -nx1 - ny0);
        float a3 = fmaf(2.f, c[nb][3], -nx1 - ny1);
        *(float2*)(out0 + col) = make_float2(ex2f(a0 * LOG2E), ex2f(a1 * LOG2E));
        *(float2*)(out1 + col) = make_float2(ex2f(a2 * LOG2E), ex2f(a3 * LOG2E));
    }
}

// ---------------- launch ----------------
extern "C" void kernel_launch(void* const* d_in, const int* in_sizes, int n_in,
                              void* d_out, int out_size) {
    const float* Wq = (const float*)d_in[0];  // rotation_params
    const float* Wk = (const float*)d_in[1];  // entangle_params
    const float* x = (const float*)d_in[2];
    const float* y = (const float*)d_in[3];
    float* out = (float*)d_out;

    cudaFuncSetAttribute(attn_kernel, cudaFuncAttributeMaxDynamicSharedMemorySize, ATTN_SMEM);
    cudaFuncSetAttribute(rbf_kernel, cudaFuncAttributeMaxDynamicSharedMemorySize, RBF_SMEM);

    proj_kernel<<<(2 * N) / 32, 256>>>(x, y, Wq, Wk);
    attn_kernel<<<128, 256, ATTN_SMEM>>>();
    rbf_kernel<<<dim3(64, 64), 256, RBF_SMEM>>>(out);
}

// round 14
// speedup vs baseline: 2.4152x; 1.5500x over previous
#include <cuda_runtime.h>
#include <cuda_bf16.h>
#include <cuda_fp16.h>
#include <math_constants.h>
#include <cstdint>

#define N 8192
#define D 64
#define LOG2E 1.4426950408889634f

// ---------------- scratch (static device memory; no allocation) ----------------
__device__ __align__(128) float g_Q[2 * N * D];  // fp32, 0.125 folded
// K packed fp16 h/l per fragment: [set][key][(ksq^(key&3))*4+tg] uint4
//   {h(2tg,2tg+1), h(2tg+8,+9), l(2tg,2tg+1), l(2tg+8,+9)}  (k within 16-chunk ksq)
__device__ __align__(128) uint4 g_kph[2 * N * 16];
// V^T packed bf16 per tile: [set][tile][d][(j^(d&3))*4+tg] uint4 (unchanged from R12)
__device__ __align__(128) uint4 g_vpk[2 * 128 * 64 * 16];
// attention out packed fp16 h/l: same fragment layout as g_kph
__device__ __align__(128) uint4 g_aph[2 * N * 16];
__device__ __align__(128) float g_nrm[2 * N];

// ---------------- helpers ----------------
__device__ __forceinline__ float ex2f(float x) {
    float r;
    asm("ex2.approx.ftz.f32 %0, %1;" : "=f"(r) : "f"(x));
    return r;
}
__device__ __forceinline__ uint32_t pkbf2(float a, float b) {
    uint32_t r;
    asm("cvt.rn.bf16x2.f32 %0, %1, %2;" : "=r"(r) : "f"(b), "f"(a));
    return r;
}
__device__ __forceinline__ float bflo_f(uint32_t v) { return __uint_as_float(v << 16); }
__device__ __forceinline__ float bfhi_f(uint32_t v) { return __uint_as_float(v & 0xffff0000u); }
// pack two floats to half2 (lo=a, hi=b); also return the rounded floats
__device__ __forceinline__ uint32_t pkh2(float a, float b) {
    __half2 h = __floats2half2_rn(a, b);
    return *(uint32_t*)&h;
}
__device__ __forceinline__ float h2lo(uint32_t v) { return __half2float(*(__half*)&v); }
__device__ __forceinline__ float h2hi(uint32_t v) {
    uint32_t t = v >> 16;
    return __half2float(*(__half*)&t);
}

__device__ __forceinline__ void mma_h(float* c, const uint32_t* a, uint32_t b0, uint32_t b1) {
    asm volatile(
        "mma.sync.aligned.m16n8k16.row.col.f32.f16.f16.f32 "
        "{%0,%1,%2,%3},{%4,%5,%6,%7},{%8,%9},{%0,%1,%2,%3};"
        : "+f"(c[0]), "+f"(c[1]), "+f"(c[2]), "+f"(c[3])
        : "r"(a[0]), "r"(a[1]), "r"(a[2]), "r"(a[3]), "r"(b0), "r"(b1));
}
__device__ __forceinline__ void mma_bf(float* c, const uint32_t* a, uint32_t b0, uint32_t b1) {
    asm volatile(
        "mma.sync.aligned.m16n8k16.row.col.f32.bf16.bf16.f32 "
        "{%0,%1,%2,%3},{%4,%5,%6,%7},{%8,%9},{%0,%1,%2,%3};"
        : "+f"(c[0]), "+f"(c[1]), "+f"(c[2]), "+f"(c[3])
        : "r"(a[0]), "r"(a[1]), "r"(a[2]), "r"(a[3]), "r"(b0), "r"(b1));
}
__device__ __forceinline__ uint32_t smem_u32(const void* p) {
    uint32_t a;
    asm("{ .reg .u64 t; cvta.to.shared.u64 t, %1; cvt.u32.u64 %0, t; }" : "=r"(a) : "l"(p));
    return a;
}
__device__ __forceinline__ void cpa16(uint32_t s, const void* g) {
    asm volatile("cp.async.cg.shared.global [%0], [%1], 16;" :: "r"(s), "l"(g));
}
__device__ __forceinline__ void cp_commit() { asm volatile("cp.async.commit_group;" ::: "memory"); }
__device__ __forceinline__ void cp_wait0() { asm volatile("cp.async.wait_group 0;" ::: "memory"); }
__device__ __forceinline__ void cp_wait1() { asm volatile("cp.async.wait_group 1;" ::: "memory"); }

// ---------------- kernel 1: projections + packed splits (32 rows/block) ----------------
__global__ __launch_bounds__(256) void proj_kernel(const float* __restrict__ x,
                                                   const float* __restrict__ y,
                                                   const float* __restrict__ Wq,
                                                   const float* __restrict__ Wk) {
    __shared__ float sW0[64][65], sW1[64][65];
    __shared__ float sIn[32][64];
    int tid = threadIdx.x;
    int base = blockIdx.x * 32;
    int set = base < N ? 0 : 1;
    int r0 = set ? base - N : base;
    const float* src = (set ? y : x) + (size_t)r0 * D;

    for (int idx = tid; idx < 4096; idx += 256) {
        sW0[idx >> 6][idx & 63] = Wq[idx];
        sW1[idx >> 6][idx & 63] = Wk[idx];
    }
#pragma unroll
    for (int e = 0; e < 8; ++e) {
        int idx = tid + 256 * e;
        int row = idx >> 6, d = idx & 63;
        float v = src[idx];
        sIn[row][d] = v;
        // V^T packed bf16 write (unchanged layout)
        int n = r0 + row;
        int tile = n >> 6, kk = n & 63;
        int jj = kk >> 4, rem = kk & 15;
        int b1 = rem >> 3, tg = (rem & 7) >> 1, lob = rem & 1;
        __nv_bfloat16 h = __float2bfloat16(v);
        __nv_bfloat16 l = __float2bfloat16(v - __bfloat162float(h));
        char* cb = (char*)g_vpk +
                   (size_t)((((set * 128 + tile) * 64 + d) * 16 + ((jj ^ (d & 3)) << 2) + tg)) * 16;
        *(__nv_bfloat16*)(cb + b1 * 4 + lob * 2) = h;
        *(__nv_bfloat16*)(cb + 8 + b1 * 4 + lob * 2) = l;
    }
    __syncthreads();

    int j = tid & 63, rl = tid >> 6;
    float fq[8], fk[8];
#pragma unroll
    for (int i = 0; i < 8; ++i) { fq[i] = 0.f; fk[i] = 0.f; }
#pragma unroll
    for (int k = 0; k < 64; ++k) {
        float wq = sW0[k][j], wk = sW1[k][j];
#pragma unroll
        for (int i = 0; i < 8; ++i) {
            float v = sIn[rl + 4 * i][k];
            fq[i] = fmaf(v, wq, fq[i]);
            fk[i] = fmaf(v, wk, fk[i]);
        }
    }
    // fp16 fragment-packed K write
    int ksq = j >> 4, rem = j & 15;
    int half_ = rem >> 3, tg = (rem & 7) >> 1, e = rem & 1;
#pragma unroll
    for (int i = 0; i < 8; ++i) {
        int n = r0 + rl + 4 * i;
        g_Q[((size_t)set * N + n) * D + j] = fq[i] * 0.125f;  // fold 1/sqrt(64)
        __half h = __float2half_rn(fk[i]);
        __half l = __float2half_rn(fk[i] - __half2float(h));
        char* kb = (char*)g_kph +
                   ((((size_t)set * N + n) * 16 + (size_t)(((ksq ^ (n & 3)) << 2) + tg)) << 4);
        *(__half*)(kb + half_ * 4 + e * 2) = h;
        *(__half*)(kb + 8 + half_ * 4 + e * 2) = l;
    }
}

// ---------------- kernel 2: flash attention, fp16-split S + bf16-split PV ----------------
// 128 blocks (2 sets x 64 q-tiles of 128 rows), 8 warps x 16 q-rows. Key tile 64.
#define SQ 0
#define SK 34816
#define SV 67584
#define ATTN_SMEM 100352

__global__ __launch_bounds__(256, 1) void attn_kernel() {
    extern __shared__ __align__(16) char sm[];
    uint32_t sb = smem_u32(sm);
    int tid = threadIdx.x, wid = tid >> 5, lane = tid & 31;
    int g = lane >> 2, tg = lane & 3;
    int set = blockIdx.x >> 6;
    int m0 = (int)(blockIdx.x & 63) * 128;

    const float* Qg = g_Q + ((size_t)set * N + m0) * D;
    const uint4* Kg = g_kph + (size_t)set * N * 16;
    const uint4* Vg = g_vpk + (size_t)set * 128 * 1024;

    // Q tile fp32 (stride 68)
    {
        float* s = (float*)(sm + SQ);
#pragma unroll
        for (int ci = tid; ci < 2048; ci += 256) {
            int row = ci >> 4, u = ci & 15;
            *(float4*)(s + row * 68 + u * 4) = *(const float4*)(Qg + row * 64 + u * 4);
        }
    }
    // prefetch tile 0
#pragma unroll
    for (int ci = tid; ci < 1024; ci += 256) {
        cpa16(sb + SK + ci * 16, Kg + ci);
        cpa16(sb + SV + ci * 16, Vg + ci);
    }
    cp_commit();
    __syncthreads();

    // Q fragments: fp16 hi/lo, m16n8k16 A layout
    uint32_t qh[4][4], ql[4][4];
    {
        const float* sQ = (const float*)(sm + SQ);
        int r0 = wid * 16 + g;
#pragma unroll
        for (int ksq = 0; ksq < 4; ++ksq) {
            int k0 = ksq * 16 + 2 * tg;
            float v00 = sQ[r0 * 68 + k0], v01 = sQ[r0 * 68 + k0 + 1];
            float v02 = sQ[r0 * 68 + k0 + 8], v03 = sQ[r0 * 68 + k0 + 9];
            float v10 = sQ[(r0 + 8) * 68 + k0], v11 = sQ[(r0 + 8) * 68 + k0 + 1];
            float v12 = sQ[(r0 + 8) * 68 + k0 + 8], v13 = sQ[(r0 + 8) * 68 + k0 + 9];
            uint32_t h;
            h = pkh2(v00, v01); qh[ksq][0] = h; ql[ksq][0] = pkh2(v00 - h2lo(h), v01 - h2hi(h));
            h = pkh2(v10, v11); qh[ksq][1] = h; ql[ksq][1] = pkh2(v10 - h2lo(h), v11 - h2hi(h));
            h = pkh2(v02, v03); qh[ksq][2] = h; ql[ksq][2] = pkh2(v02 - h2lo(h), v03 - h2hi(h));
            h = pkh2(v12, v13); qh[ksq][3] = h; ql[ksq][3] = pkh2(v12 - h2lo(h), v13 - h2hi(h));
        }
    }

    float o[8][4];
#pragma unroll
    for (int db = 0; db < 8; ++db)
#pragma unroll
        for (int q = 0; q < 4; ++q) o[db][q] = 0.f;
    float mr0 = -CUDART_INF_F, mr1 = -CUDART_INF_F;
    float l0 = 0.f, l1 = 0.f;

#pragma unroll 1
    for (int kt = 0; kt < 128; ++kt) {
        int b = kt & 1;
        if (kt < 127) {
            const uint4* kn = Kg + (size_t)(kt + 1) * 1024;
            const uint4* vn = Vg + (size_t)(kt + 1) * 1024;
#pragma unroll
            for (int ci = tid; ci < 1024; ci += 256) {
                cpa16(sb + SK + (b ^ 1) * 16384 + ci * 16, kn + ci);
                cpa16(sb + SV + (b ^ 1) * 16384 + ci * 16, vn + ci);
            }
            cp_commit();
            cp_wait1();
        } else {
            cp_wait0();
        }
        __syncthreads();
        const uint4* KP = (const uint4*)(sm + SK + b * 16384);
        const uint4* VP = (const uint4*)(sm + SV + b * 16384);

        // ---- S = Q K^T : fp16 split, 3 MMAs per uint4 load ----
        float sc[8][4];
#pragma unroll
        for (int nb = 0; nb < 8; ++nb)
#pragma unroll
            for (int q = 0; q < 4; ++q) sc[nb][q] = 0.f;
#pragma unroll
        for (int nb = 0; nb < 8; ++nb) {
            const uint4* kr = KP + (nb * 8 + g) * 16 + tg;
#pragma unroll
            for (int ksq = 0; ksq < 4; ++ksq) {
                uint4 kv = kr[(ksq ^ (g & 3)) << 2];
                mma_h(sc[nb], qh[ksq], kv.x, kv.y);
                mma_h(sc[nb], qh[ksq], kv.z, kv.w);
                mma_h(sc[nb], ql[ksq], kv.x, kv.y);
            }
        }

        // ---- online softmax ----
        float mt0 = sc[0][0], mt1 = sc[0][2];
#pragma unroll
        for (int nb = 0; nb < 8; ++nb) {
            mt0 = fmaxf(mt0, fmaxf(sc[nb][0], sc[nb][1]));
            mt1 = fmaxf(mt1, fmaxf(sc[nb][2], sc[nb][3]));
        }
        mt0 = fmaxf(mt0, __shfl_xor_sync(0xffffffffu, mt0, 1));
        mt0 = fmaxf(mt0, __shfl_xor_sync(0xffffffffu, mt0, 2));
        mt1 = fmaxf(mt1, __shfl_xor_sync(0xffffffffu, mt1, 1));
        mt1 = fmaxf(mt1, __shfl_xor_sync(0xffffffffu, mt1, 2));
        float mn0 = fmaxf(mr0, mt0), mn1 = fmaxf(mr1, mt1);
        float s0 = ex2f((mr0 - mn0) * LOG2E);
        float s1 = ex2f((mr1 - mn1) * LOG2E);
        l0 *= s0; l1 *= s1;
#pragma unroll
        for (int db = 0; db < 8; ++db) {
            o[db][0] *= s0; o[db][1] *= s0;
            o[db][2] *= s1; o[db][3] *= s1;
        }
        mr0 = mn0; mr1 = mn1;
        uint32_t ph[8][2], pl[8][2];
#pragma unroll
        for (int nb = 0; nb < 8; ++nb) {
            float p0 = ex2f((sc[nb][0] - mn0) * LOG2E);
            float p1 = ex2f((sc[nb][1] - mn0) * LOG2E);
            float p2 = ex2f((sc[nb][2] - mn1) * LOG2E);
            float p3 = ex2f((sc[nb][3] - mn1) * LOG2E);
            l0 += p0 + p1; l1 += p2 + p3;
            uint32_t h0 = pkbf2(p0, p1), h1 = pkbf2(p2, p3);
            ph[nb][0] = h0; pl[nb][0] = pkbf2(p0 - bflo_f(h0), p1 - bfhi_f(h0));
            ph[nb][1] = h1; pl[nb][1] = pkbf2(p2 - bflo_f(h1), p3 - bfhi_f(h1));
        }

        // ---- O += P V : bf16 split, 3 MMAs per uint4 load ----
#pragma unroll
        for (int j = 0; j < 4; ++j) {
            uint32_t ah[4] = {ph[2 * j][0], ph[2 * j][1], ph[2 * j + 1][0], ph[2 * j + 1][1]};
            uint32_t al[4] = {pl[2 * j][0], pl[2 * j][1], pl[2 * j + 1][0], pl[2 * j + 1][1]};
#pragma unroll
            for (int db = 0; db < 8; ++db) {
                uint4 vv = VP[(db * 8 + g) * 16 + ((j ^ (g & 3)) << 2) + tg];
                mma_bf(o[db], ah, vv.x, vv.y);
                mma_bf(o[db], ah, vv.z, vv.w);
                mma_bf(o[db], al, vv.x, vv.y);
            }
        }
        __syncthreads();
    }

    // ---- epilogue: normalize, fp16 packed splits, norms ----
    l0 += __shfl_xor_sync(0xffffffffu, l0, 1);
    l0 += __shfl_xor_sync(0xffffffffu, l0, 2);
    l1 += __shfl_xor_sync(0xffffffffu, l1, 1);
    l1 += __shfl_xor_sync(0xffffffffu, l1, 2);
    float i0 = 1.0f / l0, i1 = 1.0f / l1;
    int r0 = m0 + wid * 16 + g, r1 = r0 + 8;
    size_t row0 = (size_t)set * N + r0, row1 = (size_t)set * N + r1;
    float nr0 = 0.f, nr1 = 0.f;
#pragma unroll
    for (int db = 0; db < 8; ++db) {
        float v0 = o[db][0] * i0, v1 = o[db][1] * i0;
        float v2 = o[db][2] * i1, v3 = o[db][3] * i1;
        nr0 = fmaf(v0, v0, fmaf(v1, v1, nr0));
        nr1 = fmaf(v2, v2, fmaf(v3, v3, nr1));
        // pack row r0 (v0,v1) and row r1 (v2,v3): k = db*8 + 2tg{,+1}
        int ksq = db >> 1, half_ = db & 1;
        uint32_t h0 = pkh2(v0, v1);
        uint32_t l0p = pkh2(v0 - h2lo(h0), v1 - h2hi(h0));
        uint32_t h1 = pkh2(v2, v3);
        uint32_t l1p = pkh2(v2 - h2lo(h1), v3 - h2hi(h1));
        size_t fo0 = ((row0 * 16 + (size_t)(((ksq ^ (r0 & 3)) << 2) + tg)) << 4) + half_ * 4;
        size_t fo1 = ((row1 * 16 + (size_t)(((ksq ^ (r1 & 3)) << 2) + tg)) << 4) + half_ * 4;
        *(uint32_t*)((char*)g_aph + fo0) = h0;
        *(uint32_t*)((char*)g_aph + fo0 + 8) = l0p;
        *(uint32_t*)((char*)g_aph + fo1) = h1;
        *(uint32_t*)((char*)g_aph + fo1 + 8) = l1p;
    }
    nr0 += __shfl_xor_sync(0xffffffffu, nr0, 1);
    nr0 += __shfl_xor_sync(0xffffffffu, nr0, 2);
    nr1 += __shfl_xor_sync(0xffffffffu, nr1, 1);
    nr1 += __shfl_xor_sync(0xffffffffu, nr1, 2);
    if (tg == 0) {
        g_nrm[set * N + r0] = nr0;
        g_nrm[set * N + r1] = nr1;
    }
}

// ---------------- kernel 3: RBF via fp16-split mma.sync ----------------
#define RX 0
#define RY 32768
#define RNX 65536
#define RNY 66048
#define RBF_SMEM 66560

__global__ __launch_bounds__(256, 1) void rbf_kernel(float* __restrict__ out) {
    extern __shared__ __align__(16) char sm[];
    uint32_t sb = smem_u32(sm);
    int tid = threadIdx.x, wid = tid >> 5, lane = tid & 31;
    int g = lane >> 2, tg = lane & 3;
    int i0 = blockIdx.y * 128, j0 = blockIdx.x * 128;

    const uint4* Xg = g_aph + (size_t)i0 * 16;
    const uint4* Yg = g_aph + ((size_t)N + j0) * 16;
#pragma unroll
    for (int ci = tid; ci < 2048; ci += 256) {
        cpa16(sb + RX + ci * 16, Xg + ci);
        cpa16(sb + RY + ci * 16, Yg + ci);
    }
    cp_commit();
    if (tid < 128) {
        ((float*)(sm + RNX))[tid] = g_nrm[i0 + tid];
        ((float*)(sm + RNY))[tid] = g_nrm[N + j0 + tid];
    }
    cp_wait0();
    __syncthreads();

    const uint4* XP = (const uint4*)(sm + RX);
    const uint4* YP = (const uint4*)(sm + RY);

    // A fragments (rows r0, r0+8) assembled from two packed uint4 loads per ksq
    uint32_t ah[4][4], al[4][4];
    int r0 = wid * 16 + g;
#pragma unroll
    for (int ksq = 0; ksq < 4; ++ksq) {
        uint4 a0 = XP[r0 * 16 + (((ksq ^ (r0 & 3)) << 2) + tg)];
        uint4 a8 = XP[(r0 + 8) * 16 + (((ksq ^ (r0 & 3)) << 2) + tg)];
        ah[ksq][0] = a0.x; ah[ksq][1] = a8.x; ah[ksq][2] = a0.y; ah[ksq][3] = a8.y;
        al[ksq][0] = a0.z; al[ksq][1] = a8.z; al[ksq][2] = a0.w; al[ksq][3] = a8.w;
    }

    float c[16][4];
#pragma unroll
    for (int nb = 0; nb < 16; ++nb)
#pragma unroll
        for (int q = 0; q < 4; ++q) c[nb][q] = 0.f;

#pragma unroll
    for (int nb = 0; nb < 16; ++nb) {
        const uint4* yr = YP + (nb * 8 + g) * 16 + tg;
#pragma unroll
        for (int ksq = 0; ksq < 4; ++ksq) {
            uint4 bv = yr[(ksq ^ (g & 3)) << 2];
            mma_h(c[nb], ah[ksq], bv.x, bv.y);
            mma_h(c[nb], ah[ksq], bv.z, bv.w);
            mma_h(c[nb], al[ksq], bv.x, bv.y);
        }
    }

    const float* snx = (const float*)(sm + RNX);
    const float* sny = (const float*)(sm + RNY);
    float nx0 = snx[r0], nx1 = snx[r0 + 8];
    float* out0 = out + (size_t)(i0 + r0) * N + j0;
    float* out1 = out0 + (size_t)8 * N;
#pragma unroll
    for (int nb = 0; nb < 16; ++nb) {
        int col = nb * 8 + 2 * tg;
        float ny0 = sny[col], ny1 = sny[col + 1];
        float a0 = fmaf(2.f, c[nb][0], -nx0 - ny0);
        float a1 = fmaf(2.f, c[nb][1], -nx0 - ny1);
        float a2 = fmaf(2.f, c[nb][2], -nx1 - ny0);
        float a3 = fmaf(2.f, c[nb][3], -nx1 - ny1);
        *(float2*)(out0 + col) = make_float2(ex2f(a0 * LOG2E), ex2f(a1 * LOG2E));
        *(float2*)(out1 + col) = make_float2(ex2f(a2 * LOG2E), ex2f(a3 * LOG2E));
    }
}

// ---------------- launch ----------------
extern "C" void kernel_launch(void* const* d_in, const int* in_sizes, int n_in,
                              void* d_out, int out_size) {
    const float* Wq = (const float*)d_in[0];  // rotation_params
    const float* Wk = (const float*)d_in[1];  // entangle_params
    const float* x = (const float*)d_in[2];
    const float* y = (const float*)d_in[3];
    float* out = (float*)d_out;

    cudaFuncSetAttribute(attn_kernel, cudaFuncAttributeMaxDynamicSharedMemorySize, ATTN_SMEM);
    cudaFuncSetAttribute(rbf_kernel, cudaFuncAttributeMaxDynamicSharedMemorySize, RBF_SMEM);

    proj_kernel<<<(2 * N) / 32, 256>>>(x, y, Wq, Wk);
    attn_kernel<<<128, 256, ATTN_SMEM>>>();
    rbf_kernel<<<dim3(64, 64), 256, RBF_SMEM>>>(out);
}